// round 2
// baseline (speedup 1.0000x reference)
#include <cuda_runtime.h>
#include <math.h>

#define BSZ 4
#define TN  2048
#define CN  1024
#define HN  1024

// Scratch (allocation-free rule: __device__ globals)
__device__ float g_Q[BSZ * TN * HN];
__device__ float g_K[BSZ * TN * HN];
__device__ float g_V[BSZ * TN * HN];
__device__ float g_S[BSZ * TN * TN];

// ---------------------------------------------------------------------------
// Classic 128x128x8 SGEMM tile body, 256 threads, 8x8 per thread.
// A is [M,K] row-major. NN: B is [K,N] row-major. NT: B is [N,K] row-major.
// ---------------------------------------------------------------------------

__device__ __forceinline__ void gemm_nn_body(
    const float* __restrict__ A, int lda,
    const float* __restrict__ B, int ldb,
    float* __restrict__ C, int ldc,
    int kTiles, int blockRow, int blockCol, float scale)
{
    __shared__ float As[8][128];
    __shared__ float Bs[8][128];

    const int tid = threadIdx.x;
    const int tx = tid & 15;
    const int ty = tid >> 4;

    float acc[8][8];
#pragma unroll
    for (int i = 0; i < 8; i++)
#pragma unroll
        for (int j = 0; j < 8; j++) acc[i][j] = 0.f;

    const int aRow = tid >> 1;          // 0..127
    const int aCol = (tid & 1) << 2;    // 0 or 4
    const int bRow = tid >> 5;          // 0..7
    const int bCol = (tid & 31) << 2;   // 0..124

    const float* Aptr = A + (size_t)(blockRow * 128 + aRow) * lda + aCol;
    const float* Bptr = B + (size_t)bRow * ldb + blockCol * 128 + bCol;

    for (int kt = 0; kt < kTiles; ++kt) {
        float4 av = *(const float4*)(Aptr + kt * 8);
        As[aCol + 0][aRow] = av.x;
        As[aCol + 1][aRow] = av.y;
        As[aCol + 2][aRow] = av.z;
        As[aCol + 3][aRow] = av.w;
        float4 bv = *(const float4*)(Bptr + (size_t)kt * 8 * ldb);
        *(float4*)&Bs[bRow][bCol] = bv;
        __syncthreads();

#pragma unroll
        for (int k = 0; k < 8; k++) {
            float4 a0 = *(const float4*)&As[k][ty * 8];
            float4 a1 = *(const float4*)&As[k][ty * 8 + 4];
            float4 b0 = *(const float4*)&Bs[k][tx * 8];
            float4 b1 = *(const float4*)&Bs[k][tx * 8 + 4];
            float ra[8] = {a0.x, a0.y, a0.z, a0.w, a1.x, a1.y, a1.z, a1.w};
            float rb[8] = {b0.x, b0.y, b0.z, b0.w, b1.x, b1.y, b1.z, b1.w};
#pragma unroll
            for (int i = 0; i < 8; i++)
#pragma unroll
                for (int j = 0; j < 8; j++) acc[i][j] += ra[i] * rb[j];
        }
        __syncthreads();
    }

#pragma unroll
    for (int i = 0; i < 8; i++) {
        float* Crow = C + (size_t)(blockRow * 128 + ty * 8 + i) * ldc + blockCol * 128 + tx * 8;
        float4 v0 = {acc[i][0] * scale, acc[i][1] * scale, acc[i][2] * scale, acc[i][3] * scale};
        float4 v1 = {acc[i][4] * scale, acc[i][5] * scale, acc[i][6] * scale, acc[i][7] * scale};
        *(float4*)(Crow)     = v0;
        *(float4*)(Crow + 4) = v1;
    }
}

__device__ __forceinline__ void gemm_nt_body(
    const float* __restrict__ A, int lda,
    const float* __restrict__ B, int ldb,   // B is [N, K] row-major
    float* __restrict__ C, int ldc,
    int kTiles, int blockRow, int blockCol, float scale)
{
    __shared__ float As[8][128];
    __shared__ float Bs[8][128];

    const int tid = threadIdx.x;
    const int tx = tid & 15;
    const int ty = tid >> 4;

    float acc[8][8];
#pragma unroll
    for (int i = 0; i < 8; i++)
#pragma unroll
        for (int j = 0; j < 8; j++) acc[i][j] = 0.f;

    const int aRow = tid >> 1;
    const int aCol = (tid & 1) << 2;

    const float* Aptr = A + (size_t)(blockRow * 128 + aRow) * lda + aCol;
    const float* Bptr = B + (size_t)(blockCol * 128 + aRow) * ldb + aCol;

    for (int kt = 0; kt < kTiles; ++kt) {
        float4 av = *(const float4*)(Aptr + kt * 8);
        As[aCol + 0][aRow] = av.x;
        As[aCol + 1][aRow] = av.y;
        As[aCol + 2][aRow] = av.z;
        As[aCol + 3][aRow] = av.w;
        float4 bv = *(const float4*)(Bptr + kt * 8);
        Bs[aCol + 0][aRow] = bv.x;
        Bs[aCol + 1][aRow] = bv.y;
        Bs[aCol + 2][aRow] = bv.z;
        Bs[aCol + 3][aRow] = bv.w;
        __syncthreads();

#pragma unroll
        for (int k = 0; k < 8; k++) {
            float4 a0 = *(const float4*)&As[k][ty * 8];
            float4 a1 = *(const float4*)&As[k][ty * 8 + 4];
            float4 b0 = *(const float4*)&Bs[k][tx * 8];
            float4 b1 = *(const float4*)&Bs[k][tx * 8 + 4];
            float ra[8] = {a0.x, a0.y, a0.z, a0.w, a1.x, a1.y, a1.z, a1.w};
            float rb[8] = {b0.x, b0.y, b0.z, b0.w, b1.x, b1.y, b1.z, b1.w};
#pragma unroll
            for (int i = 0; i < 8; i++)
#pragma unroll
                for (int j = 0; j < 8; j++) acc[i][j] += ra[i] * rb[j];
        }
        __syncthreads();
    }

#pragma unroll
    for (int i = 0; i < 8; i++) {
        float* Crow = C + (size_t)(blockRow * 128 + ty * 8 + i) * ldc + blockCol * 128 + tx * 8;
        float4 v0 = {acc[i][0] * scale, acc[i][1] * scale, acc[i][2] * scale, acc[i][3] * scale};
        float4 v1 = {acc[i][4] * scale, acc[i][5] * scale, acc[i][6] * scale, acc[i][7] * scale};
        *(float4*)(Crow)     = v0;
        *(float4*)(Crow + 4) = v1;
    }
}

// ---------------------------------------------------------------------------
// Kernel 1: QKV projections. grid = (HN/128, (BSZ*TN)/128, 3)
// ---------------------------------------------------------------------------
__global__ void __launch_bounds__(256)
qkv_gemm(const float* __restrict__ X,
         const float* __restrict__ Wk,
         const float* __restrict__ Wq,
         const float* __restrict__ Wv)
{
    const float* W;
    float* Out;
    if (blockIdx.z == 0)      { W = Wq; Out = g_Q; }
    else if (blockIdx.z == 1) { W = Wk; Out = g_K; }
    else                      { W = Wv; Out = g_V; }
    gemm_nn_body(X, CN, W, HN, Out, HN, CN / 8, blockIdx.y, blockIdx.x, 1.0f);
}

// ---------------------------------------------------------------------------
// Kernel 2: S = Q K^T * scale, causal block skipping. grid = (16,16,BSZ)
// ---------------------------------------------------------------------------
__global__ void __launch_bounds__(256)
scores_kernel()
{
    if (blockIdx.x > blockIdx.y) return;  // entirely above diagonal: never read
    const int b = blockIdx.z;
    const float* Q = g_Q + (size_t)b * TN * HN;
    const float* K = g_K + (size_t)b * TN * HN;
    float* S = g_S + (size_t)b * TN * TN;
    gemm_nt_body(Q, HN, K, HN, S, TN, HN / 8, blockIdx.y, blockIdx.x, 0.03125f);
}

// ---------------------------------------------------------------------------
// Kernel 3: causal softmax, in place on S. grid = (TN, BSZ), 256 threads
// Zero-pads (t, align_up(t+1,128)) so PV can consume full 128-blocks.
// ---------------------------------------------------------------------------
__global__ void __launch_bounds__(256)
softmax_kernel()
{
    const int t = blockIdx.x;
    const int b = blockIdx.y;
    float* row = g_S + ((size_t)b * TN + t) * TN;
    const int n = t + 1;
    const int tid = threadIdx.x;

    __shared__ float red[8];

    // --- max ---
    float m = -INFINITY;
    for (int i = tid; i < n; i += 256) m = fmaxf(m, row[i]);
#pragma unroll
    for (int o = 16; o > 0; o >>= 1) m = fmaxf(m, __shfl_xor_sync(0xffffffffu, m, o));
    if ((tid & 31) == 0) red[tid >> 5] = m;
    __syncthreads();
    m = -INFINITY;
#pragma unroll
    for (int w = 0; w < 8; w++) m = fmaxf(m, red[w]);
    __syncthreads();

    // --- exp + sum ---
    float s = 0.f;
    for (int i = tid; i < n; i += 256) {
        float e = expf(row[i] - m);
        row[i] = e;
        s += e;
    }
#pragma unroll
    for (int o = 16; o > 0; o >>= 1) s += __shfl_xor_sync(0xffffffffu, s, o);
    if ((tid & 31) == 0) red[tid >> 5] = s;
    __syncthreads();
    s = 0.f;
#pragma unroll
    for (int w = 0; w < 8; w++) s += red[w];

    const float inv = 1.0f / s;
    for (int i = tid; i < n; i += 256) row[i] *= inv;

    // zero-pad to end of this row's 128-block so PV reads clean tiles
    const int npad = ((t >> 7) + 1) << 7;
    for (int i = n + tid; i < npad; i += 256) row[i] = 0.f;
}

// ---------------------------------------------------------------------------
// Kernel 4: O = P V, k-loop truncated at the diagonal. grid = (HN/128, 16, BSZ)
// ---------------------------------------------------------------------------
__global__ void __launch_bounds__(256)
pv_kernel(float* __restrict__ out)
{
    const int b = blockIdx.z;
    const float* P = g_S + (size_t)b * TN * TN;
    const float* V = g_V + (size_t)b * TN * HN;
    float* O = out + (size_t)b * TN * HN;
    const int kTiles = (blockIdx.y + 1) * 16;   // s < (blockRow+1)*128
    gemm_nn_body(P, TN, V, HN, O, HN, kTiles, blockIdx.y, blockIdx.x, 1.0f);
}

// ---------------------------------------------------------------------------
extern "C" void kernel_launch(void* const* d_in, const int* in_sizes, int n_in,
                              void* d_out, int out_size)
{
    const float* x  = (const float*)d_in[0];
    const float* Wk = (const float*)d_in[1];
    const float* Wq = (const float*)d_in[2];
    const float* Wv = (const float*)d_in[3];
    float* out = (float*)d_out;

    qkv_gemm<<<dim3(HN / 128, (BSZ * TN) / 128, 3), 256>>>(x, Wk, Wq, Wv);
    scores_kernel<<<dim3(TN / 128, TN / 128, BSZ), 256>>>();
    softmax_kernel<<<dim3(TN, BSZ), 256>>>();
    pv_kernel<<<dim3(HN / 128, TN / 128, BSZ), 256>>>(out);
}

// round 8
// speedup vs baseline: 1.5156x; 1.5156x over previous
#include <cuda_runtime.h>
#include <mma.h>
#include <math.h>
#include <stdint.h>

using namespace nvcuda;

#define BSZ 4
#define TN  2048
#define CN  1024
#define HN  1024

// Scratch (allocation-free rule: __device__ globals)
__device__ float g_Q[BSZ * TN * HN];
__device__ float g_K[BSZ * TN * HN];
__device__ float g_V[BSZ * TN * HN];
__device__ float g_S[BSZ * TN * TN];

// ---------------------------------------------------------------------------
// cp.async helpers (LDGSTS — supported on base sm_103 target)
// ---------------------------------------------------------------------------
__device__ __forceinline__ uint32_t smem_u32(const void* p) {
    uint32_t a;
    asm("{ .reg .u64 t; cvta.to.shared.u64 t, %1; cvt.u32.u64 %0, t; }" : "=r"(a) : "l"(p));
    return a;
}
#define CP_ASYNC16(dst_u32, src_ptr) \
    asm volatile("cp.async.cg.shared.global [%0], [%1], 16;" :: "r"(dst_u32), "l"(src_ptr))
#define CP_COMMIT() asm volatile("cp.async.commit_group;" ::: "memory")
#define CP_WAIT(N)  asm volatile("cp.async.wait_group %0;" :: "n"(N) : "memory")

// ---------------------------------------------------------------------------
// Tile geometry: BM=BN=128, BK=32. 8 warps (4 row x 2 col), warp = 32x64.
// SMEM: A chunk 128x32 @ld36, B chunk either 32x128 @ld132 (B_KN) or
// 128x32 @ld36 (B_NK). Double buffered. Buffer stride 9216 floats.
// ---------------------------------------------------------------------------
#define A_LD 36
#define B_LD_KN 132
#define BUF_FLOATS 9216
#define SMEM_BYTES (2 * BUF_FLOATS * 4)   // 73728

template <bool B_KN>
__device__ __forceinline__ void wmma_tile(
    const float* __restrict__ A, int lda,
    const float* __restrict__ B, int ldb,
    float* __restrict__ C, int ldc,
    int kChunks, int br, int bc, float scale)
{
    extern __shared__ float sm[];
    const uint32_t sm_b = smem_u32(sm);
    const int tid = threadIdx.x;
    const int wid = tid >> 5;
    const int wr = wid >> 1;     // 0..3 (32-row band)
    const int wc = wid & 1;      // 0..1 (64-col band)

    float* AsF[2] = { sm,        sm + BUF_FLOATS };
    float* BsF[2] = { sm + 4608, sm + BUF_FLOATS + 4608 };
    const uint32_t AsU[2] = { sm_b,            sm_b + BUF_FLOATS * 4 };
    const uint32_t BsU[2] = { sm_b + 4608 * 4, sm_b + (BUF_FLOATS + 4608) * 4 };

    wmma::fragment<wmma::accumulator, 16, 16, 8, float> acc[2][4];
#pragma unroll
    for (int i = 0; i < 2; i++)
#pragma unroll
        for (int j = 0; j < 4; j++) wmma::fill_fragment(acc[i][j], 0.0f);

    // ---- async load issue for chunk kc into buffer b ----
    auto issue_load = [&](int b, int kc) {
        // A: 128 rows x 32 cols
        const float* Ab = A + (size_t)(br * 128) * lda + kc * 32;
#pragma unroll
        for (int p = 0; p < 4; ++p) {
            int idx = p * 256 + tid;
            int row = idx >> 3, c4 = idx & 7;
            CP_ASYNC16(AsU[b] + (row * A_LD + c4 * 4) * 4,
                       Ab + (size_t)row * lda + c4 * 4);
        }
        if (B_KN) {
            // B: [K,N] rows kc*32..+31, cols bc*128..+127
            const float* Bb = B + (size_t)(kc * 32) * ldb + bc * 128;
#pragma unroll
            for (int p = 0; p < 4; ++p) {
                int idx = p * 256 + tid;
                int row = idx >> 5, c4 = idx & 31;
                CP_ASYNC16(BsU[b] + (row * B_LD_KN + c4 * 4) * 4,
                           Bb + (size_t)row * ldb + c4 * 4);
            }
        } else {
            // B: [N,K] rows bc*128..+127, cols kc*32..+31 (same pattern as A)
            const float* Bb = B + (size_t)(bc * 128) * ldb + kc * 32;
#pragma unroll
            for (int p = 0; p < 4; ++p) {
                int idx = p * 256 + tid;
                int row = idx >> 3, c4 = idx & 7;
                CP_ASYNC16(BsU[b] + (row * A_LD + c4 * 4) * 4,
                           Bb + (size_t)row * ldb + c4 * 4);
            }
        }
        CP_COMMIT();
    };

    issue_load(0, 0);

    int cur = 0;
    for (int kc = 0; kc < kChunks; ++kc) {
        if (kc + 1 < kChunks) { issue_load(cur ^ 1, kc + 1); CP_WAIT(1); }
        else                  { CP_WAIT(0); }
        __syncthreads();

        const float* Asb = AsF[cur];
        const float* Bsb = BsF[cur];
#pragma unroll
        for (int ks = 0; ks < 4; ++ks) {
            const int k0 = ks * 8;
            wmma::fragment<wmma::matrix_a, 16, 16, 8, wmma::precision::tf32, wmma::row_major> af[2];
#pragma unroll
            for (int i = 0; i < 2; i++) {
                wmma::load_matrix_sync(af[i], Asb + (wr * 32 + i * 16) * A_LD + k0, A_LD);
#pragma unroll
                for (int t = 0; t < af[i].num_elements; t++)
                    af[i].x[t] = wmma::__float_to_tf32(af[i].x[t]);
            }
            if (B_KN) {
                wmma::fragment<wmma::matrix_b, 16, 16, 8, wmma::precision::tf32, wmma::row_major> bf[4];
#pragma unroll
                for (int j = 0; j < 4; j++) {
                    wmma::load_matrix_sync(bf[j], Bsb + k0 * B_LD_KN + wc * 64 + j * 16, B_LD_KN);
#pragma unroll
                    for (int t = 0; t < bf[j].num_elements; t++)
                        bf[j].x[t] = wmma::__float_to_tf32(bf[j].x[t]);
                }
#pragma unroll
                for (int i = 0; i < 2; i++)
#pragma unroll
                    for (int j = 0; j < 4; j++)
                        wmma::mma_sync(acc[i][j], af[i], bf[j], acc[i][j]);
            } else {
                wmma::fragment<wmma::matrix_b, 16, 16, 8, wmma::precision::tf32, wmma::col_major> bf[4];
#pragma unroll
                for (int j = 0; j < 4; j++) {
                    wmma::load_matrix_sync(bf[j], Bsb + (wc * 64 + j * 16) * A_LD + k0, A_LD);
#pragma unroll
                    for (int t = 0; t < bf[j].num_elements; t++)
                        bf[j].x[t] = wmma::__float_to_tf32(bf[j].x[t]);
                }
#pragma unroll
                for (int i = 0; i < 2; i++)
#pragma unroll
                    for (int j = 0; j < 4; j++)
                        wmma::mma_sync(acc[i][j], af[i], bf[j], acc[i][j]);
            }
        }
        __syncthreads();
        cur ^= 1;
    }

    // ---- store ----
#pragma unroll
    for (int i = 0; i < 2; i++)
#pragma unroll
        for (int j = 0; j < 4; j++) {
#pragma unroll
            for (int t = 0; t < acc[i][j].num_elements; t++) acc[i][j].x[t] *= scale;
            float* cp = C + (size_t)(br * 128 + wr * 32 + i * 16) * ldc + bc * 128 + wc * 64 + j * 16;
            wmma::store_matrix_sync(cp, acc[i][j], ldc, wmma::mem_row_major);
        }
}

// ---------------------------------------------------------------------------
// Kernel 1: QKV projections. grid = (HN/128, 64, 3). W is [C,H] = [K,N]
// ---------------------------------------------------------------------------
__global__ void __launch_bounds__(256)
qkv_wmma(const float* __restrict__ X,
         const float* __restrict__ Wk,
         const float* __restrict__ Wq,
         const float* __restrict__ Wv)
{
    const float* W;
    float* Out;
    if (blockIdx.z == 0)      { W = Wq; Out = g_Q; }
    else if (blockIdx.z == 1) { W = Wk; Out = g_K; }
    else                      { W = Wv; Out = g_V; }
    wmma_tile<true>(X, CN, W, HN, Out, HN, CN / 32, blockIdx.y, blockIdx.x, 1.0f);
}

// ---------------------------------------------------------------------------
// Kernel 2: S = Q K^T * scale, causal block skip. grid = (16,16,BSZ). B=[N,K]
// ---------------------------------------------------------------------------
__global__ void __launch_bounds__(256)
scores_wmma()
{
    if (blockIdx.x > blockIdx.y) return;
    const int b = blockIdx.z;
    const float* Q = g_Q + (size_t)b * TN * HN;
    const float* K = g_K + (size_t)b * TN * HN;
    float* S = g_S + (size_t)b * TN * TN;
    wmma_tile<false>(Q, HN, K, HN, S, TN, HN / 32, blockIdx.y, blockIdx.x, 0.03125f);
}

// ---------------------------------------------------------------------------
// Kernel 3: causal softmax, in place, zero-pads to 128 multiple. grid (TN,BSZ)
// ---------------------------------------------------------------------------
__global__ void __launch_bounds__(256)
softmax_kernel()
{
    const int t = blockIdx.x;
    const int b = blockIdx.y;
    float* row = g_S + ((size_t)b * TN + t) * TN;
    const int n = t + 1;
    const int tid = threadIdx.x;

    __shared__ float red[8];

    float m = -INFINITY;
    for (int i = tid; i < n; i += 256) m = fmaxf(m, row[i]);
#pragma unroll
    for (int o = 16; o > 0; o >>= 1) m = fmaxf(m, __shfl_xor_sync(0xffffffffu, m, o));
    if ((tid & 31) == 0) red[tid >> 5] = m;
    __syncthreads();
    m = -INFINITY;
#pragma unroll
    for (int w = 0; w < 8; w++) m = fmaxf(m, red[w]);
    __syncthreads();

    float s = 0.f;
    for (int i = tid; i < n; i += 256) {
        float e = expf(row[i] - m);
        row[i] = e;
        s += e;
    }
#pragma unroll
    for (int o = 16; o > 0; o >>= 1) s += __shfl_xor_sync(0xffffffffu, s, o);
    if ((tid & 31) == 0) red[tid >> 5] = s;
    __syncthreads();
    s = 0.f;
#pragma unroll
    for (int w = 0; w < 8; w++) s += red[w];

    const float inv = 1.0f / s;
    for (int i = tid; i < n; i += 256) row[i] *= inv;

    const int npad = ((t >> 7) + 1) << 7;
    for (int i = n + tid; i < npad; i += 256) row[i] = 0.f;
}

// ---------------------------------------------------------------------------
// Kernel 4: O = P V, k truncated at diagonal. grid (8,16,BSZ). V = [K,N]
// ---------------------------------------------------------------------------
__global__ void __launch_bounds__(256)
pv_wmma(float* __restrict__ out)
{
    const int b = blockIdx.z;
    const float* P = g_S + (size_t)b * TN * TN;
    const float* V = g_V + (size_t)b * TN * HN;
    float* O = out + (size_t)b * TN * HN;
    const int kChunks = (blockIdx.y + 1) * 4;   // cover s < (blockRow+1)*128
    wmma_tile<true>(P, TN, V, HN, O, HN, kChunks, blockIdx.y, blockIdx.x, 1.0f);
}

// ---------------------------------------------------------------------------
extern "C" void kernel_launch(void* const* d_in, const int* in_sizes, int n_in,
                              void* d_out, int out_size)
{
    const float* x  = (const float*)d_in[0];
    const float* Wk = (const float*)d_in[1];
    const float* Wq = (const float*)d_in[2];
    const float* Wv = (const float*)d_in[3];
    float* out = (float*)d_out;

    cudaFuncSetAttribute(qkv_wmma,    cudaFuncAttributeMaxDynamicSharedMemorySize, SMEM_BYTES);
    cudaFuncSetAttribute(scores_wmma, cudaFuncAttributeMaxDynamicSharedMemorySize, SMEM_BYTES);
    cudaFuncSetAttribute(pv_wmma,     cudaFuncAttributeMaxDynamicSharedMemorySize, SMEM_BYTES);

    qkv_wmma<<<dim3(HN / 128, (BSZ * TN) / 128, 3), 256, SMEM_BYTES>>>(x, Wk, Wq, Wv);
    scores_wmma<<<dim3(TN / 128, TN / 128, BSZ), 256, SMEM_BYTES>>>();
    softmax_kernel<<<dim3(TN, BSZ), 256>>>();
    pv_wmma<<<dim3(HN / 128, TN / 128, BSZ), 256, SMEM_BYTES>>>(out);
}

// round 9
// speedup vs baseline: 1.6792x; 1.1080x over previous
#include <cuda_runtime.h>
#include <mma.h>
#include <math.h>
#include <stdint.h>

using namespace nvcuda;

#define BSZ 4
#define TN  2048
#define CN  1024
#define HN  1024

// Scratch (allocation-free rule: __device__ globals)
__device__ float g_Q[BSZ * TN * HN];
__device__ float g_K[BSZ * TN * HN];
__device__ float g_V[BSZ * TN * HN];
__device__ float g_S[BSZ * TN * TN];

// ---------------------------------------------------------------------------
// helpers
// ---------------------------------------------------------------------------
__device__ __forceinline__ uint32_t smem_u32(const void* p) {
    uint32_t a;
    asm("{ .reg .u64 t; cvta.to.shared.u64 t, %1; cvt.u32.u64 %0, t; }" : "=r"(a) : "l"(p));
    return a;
}
__device__ __forceinline__ float tf32r(float x) {
    float r;
    asm("cvt.rna.tf32.f32 %0, %1;" : "=f"(r) : "f"(x));
    return r;
}
#define CP_ASYNC16(dst_u32, src_ptr) \
    asm volatile("cp.async.cg.shared.global [%0], [%1], 16;" :: "r"(dst_u32), "l"(src_ptr))
#define CP_COMMIT() asm volatile("cp.async.commit_group;" ::: "memory")
#define CP_WAIT(N)  asm volatile("cp.async.wait_group %0;" :: "n"(N) : "memory")

// ---------------------------------------------------------------------------
// Tile geometry: BM=BN=128, BK=32. 8 warps (4 row x 2 col), warp = 32x64.
// SMEM: A chunk 128x32 @ld36, B chunk either 32x128 @ld132 (B_KN) or
// 128x32 @ld36 (B_NK). Double buffered. Buffer stride 9216 floats.
// ---------------------------------------------------------------------------
#define A_LD 36
#define B_LD_KN 132
#define BUF_FLOATS 9216
#define SMEM_BYTES (2 * BUF_FLOATS * 4)   // 73728

// CVT: run per-element tf32 rounding on loaded fragments (needed only when
//      the source matrices are raw fp32; scratch written by us is pre-rounded).
// ROUND_OUT: round the fp32 accumulator output to tf32 at store (so consumers
//      can skip CVT).
template <bool B_KN, bool CVT, bool ROUND_OUT>
__device__ __forceinline__ void wmma_tile(
    const float* __restrict__ A, int lda,
    const float* __restrict__ B, int ldb,
    float* __restrict__ C, int ldc,
    int kChunks, int br, int bc, float scale)
{
    extern __shared__ float sm[];
    const uint32_t sm_b = smem_u32(sm);
    const int tid = threadIdx.x;
    const int wid = tid >> 5;
    const int wr = wid >> 1;     // 0..3 (32-row band)
    const int wc = wid & 1;      // 0..1 (64-col band)

    float* AsF[2] = { sm,        sm + BUF_FLOATS };
    float* BsF[2] = { sm + 4608, sm + BUF_FLOATS + 4608 };
    const uint32_t AsU[2] = { sm_b,            sm_b + BUF_FLOATS * 4 };
    const uint32_t BsU[2] = { sm_b + 4608 * 4, sm_b + (BUF_FLOATS + 4608) * 4 };

    wmma::fragment<wmma::accumulator, 16, 16, 8, float> acc[2][4];
#pragma unroll
    for (int i = 0; i < 2; i++)
#pragma unroll
        for (int j = 0; j < 4; j++) wmma::fill_fragment(acc[i][j], 0.0f);

    // ---- async load issue for chunk kc into buffer b ----
    auto issue_load = [&](int b, int kc) {
        const float* Ab = A + (size_t)(br * 128) * lda + kc * 32;
#pragma unroll
        for (int p = 0; p < 4; ++p) {
            int idx = p * 256 + tid;
            int row = idx >> 3, c4 = idx & 7;
            CP_ASYNC16(AsU[b] + (row * A_LD + c4 * 4) * 4,
                       Ab + (size_t)row * lda + c4 * 4);
        }
        if (B_KN) {
            const float* Bb = B + (size_t)(kc * 32) * ldb + bc * 128;
#pragma unroll
            for (int p = 0; p < 4; ++p) {
                int idx = p * 256 + tid;
                int row = idx >> 5, c4 = idx & 31;
                CP_ASYNC16(BsU[b] + (row * B_LD_KN + c4 * 4) * 4,
                           Bb + (size_t)row * ldb + c4 * 4);
            }
        } else {
            const float* Bb = B + (size_t)(bc * 128) * ldb + kc * 32;
#pragma unroll
            for (int p = 0; p < 4; ++p) {
                int idx = p * 256 + tid;
                int row = idx >> 3, c4 = idx & 7;
                CP_ASYNC16(BsU[b] + (row * A_LD + c4 * 4) * 4,
                           Bb + (size_t)row * ldb + c4 * 4);
            }
        }
        CP_COMMIT();
    };

    issue_load(0, 0);

    int cur = 0;
    for (int kc = 0; kc < kChunks; ++kc) {
        if (kc + 1 < kChunks) { issue_load(cur ^ 1, kc + 1); CP_WAIT(1); }
        else                  { CP_WAIT(0); }
        __syncthreads();

        const float* Asb = AsF[cur];
        const float* Bsb = BsF[cur];
#pragma unroll
        for (int ks = 0; ks < 4; ++ks) {
            const int k0 = ks * 8;
            wmma::fragment<wmma::matrix_a, 16, 16, 8, wmma::precision::tf32, wmma::row_major> af[2];
#pragma unroll
            for (int i = 0; i < 2; i++) {
                wmma::load_matrix_sync(af[i], Asb + (wr * 32 + i * 16) * A_LD + k0, A_LD);
                if (CVT) {
#pragma unroll
                    for (int t = 0; t < af[i].num_elements; t++)
                        af[i].x[t] = wmma::__float_to_tf32(af[i].x[t]);
                }
            }
            if (B_KN) {
                wmma::fragment<wmma::matrix_b, 16, 16, 8, wmma::precision::tf32, wmma::row_major> bf[4];
#pragma unroll
                for (int j = 0; j < 4; j++) {
                    wmma::load_matrix_sync(bf[j], Bsb + k0 * B_LD_KN + wc * 64 + j * 16, B_LD_KN);
                    if (CVT) {
#pragma unroll
                        for (int t = 0; t < bf[j].num_elements; t++)
                            bf[j].x[t] = wmma::__float_to_tf32(bf[j].x[t]);
                    }
                }
#pragma unroll
                for (int i = 0; i < 2; i++)
#pragma unroll
                    for (int j = 0; j < 4; j++)
                        wmma::mma_sync(acc[i][j], af[i], bf[j], acc[i][j]);
            } else {
                wmma::fragment<wmma::matrix_b, 16, 16, 8, wmma::precision::tf32, wmma::col_major> bf[4];
#pragma unroll
                for (int j = 0; j < 4; j++) {
                    wmma::load_matrix_sync(bf[j], Bsb + (wc * 64 + j * 16) * A_LD + k0, A_LD);
                    if (CVT) {
#pragma unroll
                        for (int t = 0; t < bf[j].num_elements; t++)
                            bf[j].x[t] = wmma::__float_to_tf32(bf[j].x[t]);
                    }
                }
#pragma unroll
                for (int i = 0; i < 2; i++)
#pragma unroll
                    for (int j = 0; j < 4; j++)
                        wmma::mma_sync(acc[i][j], af[i], bf[j], acc[i][j]);
            }
        }
        __syncthreads();
        cur ^= 1;
    }

    // ---- store ----
#pragma unroll
    for (int i = 0; i < 2; i++)
#pragma unroll
        for (int j = 0; j < 4; j++) {
#pragma unroll
            for (int t = 0; t < acc[i][j].num_elements; t++) {
                float v = acc[i][j].x[t] * scale;
                acc[i][j].x[t] = ROUND_OUT ? tf32r(v) : v;
            }
            float* cp = C + (size_t)(br * 128 + wr * 32 + i * 16) * ldc + bc * 128 + wc * 64 + j * 16;
            wmma::store_matrix_sync(cp, acc[i][j], ldc, wmma::mem_row_major);
        }
}

// ---------------------------------------------------------------------------
// Kernel 1: QKV projections. grid = (HN/128, 64, 3). W is [C,H] = [K,N]
// X/W are raw fp32 -> CVT. Outputs pre-rounded to tf32 -> consumers skip CVT.
// ---------------------------------------------------------------------------
__global__ void __launch_bounds__(256, 2)
qkv_wmma(const float* __restrict__ X,
         const float* __restrict__ Wk,
         const float* __restrict__ Wq,
         const float* __restrict__ Wv)
{
    const float* W;
    float* Out;
    if (blockIdx.z == 0)      { W = Wq; Out = g_Q; }
    else if (blockIdx.z == 1) { W = Wk; Out = g_K; }
    else                      { W = Wv; Out = g_V; }
    wmma_tile<true, true, true>(X, CN, W, HN, Out, HN, CN / 32, blockIdx.y, blockIdx.x, 1.0f);
}

// ---------------------------------------------------------------------------
// Kernel 2: S = Q K^T * scale, causal block skip. grid = (16,16,BSZ). B=[N,K]
// Q/K pre-rounded -> no CVT. S stays fp32 (softmax consumes it).
// ---------------------------------------------------------------------------
__global__ void __launch_bounds__(256, 2)
scores_wmma()
{
    if (blockIdx.x > blockIdx.y) return;
    const int b = blockIdx.z;
    const float* Q = g_Q + (size_t)b * TN * HN;
    const float* K = g_K + (size_t)b * TN * HN;
    float* S = g_S + (size_t)b * TN * TN;
    wmma_tile<false, false, false>(Q, HN, K, HN, S, TN, HN / 32, blockIdx.y, blockIdx.x, 0.03125f);
}

// ---------------------------------------------------------------------------
// Kernel 3: causal softmax, in place, zero-pads to 128 multiple. grid (TN,BSZ)
// Writes P pre-rounded to tf32 so pv skips CVT.
// ---------------------------------------------------------------------------
__global__ void __launch_bounds__(256)
softmax_kernel()
{
    const int t = blockIdx.x;
    const int b = blockIdx.y;
    float* row = g_S + ((size_t)b * TN + t) * TN;
    const int n = t + 1;
    const int tid = threadIdx.x;

    __shared__ float red[8];

    float m = -INFINITY;
    for (int i = tid; i < n; i += 256) m = fmaxf(m, row[i]);
#pragma unroll
    for (int o = 16; o > 0; o >>= 1) m = fmaxf(m, __shfl_xor_sync(0xffffffffu, m, o));
    if ((tid & 31) == 0) red[tid >> 5] = m;
    __syncthreads();
    m = -INFINITY;
#pragma unroll
    for (int w = 0; w < 8; w++) m = fmaxf(m, red[w]);
    __syncthreads();

    float s = 0.f;
    for (int i = tid; i < n; i += 256) {
        float e = expf(row[i] - m);
        row[i] = e;
        s += e;
    }
#pragma unroll
    for (int o = 16; o > 0; o >>= 1) s += __shfl_xor_sync(0xffffffffu, s, o);
    if ((tid & 31) == 0) red[tid >> 5] = s;
    __syncthreads();
    s = 0.f;
#pragma unroll
    for (int w = 0; w < 8; w++) s += red[w];

    const float inv = 1.0f / s;
    for (int i = tid; i < n; i += 256) row[i] = tf32r(row[i] * inv);

    const int npad = ((t >> 7) + 1) << 7;
    for (int i = n + tid; i < npad; i += 256) row[i] = 0.f;
}

// ---------------------------------------------------------------------------
// Kernel 4: O = P V, k truncated at diagonal. grid (8,16,BSZ). V = [K,N]
// P/V pre-rounded -> no CVT. Output fp32.
// ---------------------------------------------------------------------------
__global__ void __launch_bounds__(256, 2)
pv_wmma(float* __restrict__ out)
{
    const int b = blockIdx.z;
    const float* P = g_S + (size_t)b * TN * TN;
    const float* V = g_V + (size_t)b * TN * HN;
    float* O = out + (size_t)b * TN * HN;
    const int kChunks = (blockIdx.y + 1) * 4;   // cover s < (blockRow+1)*128
    wmma_tile<true, false, false>(P, TN, V, HN, O, HN, kChunks, blockIdx.y, blockIdx.x, 1.0f);
}

// ---------------------------------------------------------------------------
extern "C" void kernel_launch(void* const* d_in, const int* in_sizes, int n_in,
                              void* d_out, int out_size)
{
    const float* x  = (const float*)d_in[0];
    const float* Wk = (const float*)d_in[1];
    const float* Wq = (const float*)d_in[2];
    const float* Wv = (const float*)d_in[3];
    float* out = (float*)d_out;

    cudaFuncSetAttribute(qkv_wmma,    cudaFuncAttributeMaxDynamicSharedMemorySize, SMEM_BYTES);
    cudaFuncSetAttribute(scores_wmma, cudaFuncAttributeMaxDynamicSharedMemorySize, SMEM_BYTES);
    cudaFuncSetAttribute(pv_wmma,     cudaFuncAttributeMaxDynamicSharedMemorySize, SMEM_BYTES);

    qkv_wmma<<<dim3(HN / 128, (BSZ * TN) / 128, 3), 256, SMEM_BYTES>>>(x, Wk, Wq, Wv);
    scores_wmma<<<dim3(TN / 128, TN / 128, BSZ), 256, SMEM_BYTES>>>();
    softmax_kernel<<<dim3(TN, BSZ), 256>>>();
    pv_wmma<<<dim3(HN / 128, TN / 128, BSZ), 256, SMEM_BYTES>>>(out);
}

// round 10
// speedup vs baseline: 4.4903x; 2.6740x over previous
#include <cuda_runtime.h>
#include <cuda_fp16.h>
#include <mma.h>
#include <math.h>
#include <stdint.h>

using namespace nvcuda;

#define BSZ 4
#define TN  2048
#define CN  1024
#define HN  1024

// fp32 scratch
__device__ float g_S[BSZ * TN * TN];
// fp16 scratch
__device__ __half g_Xh[BSZ * TN * CN];
__device__ __half g_Wh[3][CN * HN];
__device__ __half g_Qh[BSZ * TN * HN];
__device__ __half g_Kh[BSZ * TN * HN];
__device__ __half g_Vh[BSZ * TN * HN];
__device__ __half g_Ph[BSZ * TN * TN];

// ---------------------------------------------------------------------------
__device__ __forceinline__ uint32_t smem_u32(const void* p) {
    uint32_t a;
    asm("{ .reg .u64 t; cvta.to.shared.u64 t, %1; cvt.u32.u64 %0, t; }" : "=r"(a) : "l"(p));
    return a;
}
#define CP_ASYNC16(dst_u32, src_ptr) \
    asm volatile("cp.async.cg.shared.global [%0], [%1], 16;" :: "r"(dst_u32), "l"(src_ptr))
#define CP_COMMIT() asm volatile("cp.async.commit_group;" ::: "memory")
#define CP_WAIT(N)  asm volatile("cp.async.wait_group %0;" :: "n"(N) : "memory")

// ---------------------------------------------------------------------------
// fp16 tile: BM=BN=128, BK=64. 8 warps (4x2), warp=32x64, wmma m16n16k16.
// A smem [128][72] halves; B_KN smem [64][136]; B_NK smem [128][72].
// 72*2=144B, 136*2=272B: odd multiples of 16B -> LDSM conflict-free.
// ---------------------------------------------------------------------------
#define A_LDH 72
#define B_LDH_KN 136
#define ABUF_BYTES (128 * A_LDH * 2)          // 18432
#define BUF_STRIDE (2 * ABUF_BYTES)           // 36864 (covers worst-case B)
#define SMEM_BYTES (2 * BUF_STRIDE)           // 73728
#define STG_LD 132                            // fp32 staging ld (epilogue)

template <bool B_KN, bool OUT_HALF>
__device__ __forceinline__ void wmma_tile_h(
    const __half* __restrict__ A, int lda,
    const __half* __restrict__ B, int ldb,
    float* __restrict__ Cf, __half* __restrict__ Ch, int ldc,
    int kChunks, int br, int bc, float scale)
{
    extern __shared__ char smc[];
    const uint32_t sm_b = smem_u32(smc);
    const int tid = threadIdx.x;
    const int wid = tid >> 5;
    const int wr = wid >> 1;     // 0..3
    const int wc = wid & 1;      // 0..1

    const __half* AsH[2] = { (const __half*)smc,
                             (const __half*)(smc + BUF_STRIDE) };
    const __half* BsH[2] = { (const __half*)(smc + ABUF_BYTES),
                             (const __half*)(smc + BUF_STRIDE + ABUF_BYTES) };
    const uint32_t AsU[2] = { sm_b, sm_b + BUF_STRIDE };
    const uint32_t BsU[2] = { sm_b + ABUF_BYTES, sm_b + BUF_STRIDE + ABUF_BYTES };

    wmma::fragment<wmma::accumulator, 16, 16, 16, float> acc[2][4];
#pragma unroll
    for (int i = 0; i < 2; i++)
#pragma unroll
        for (int j = 0; j < 4; j++) wmma::fill_fragment(acc[i][j], 0.0f);

    auto issue_load = [&](int b, int kc) {
        // A chunk: 128 rows x 64 halves
#pragma unroll
        for (int p = 0; p < 4; ++p) {
            int idx = p * 256 + tid;
            int row = idx >> 3, c8 = idx & 7;
            CP_ASYNC16(AsU[b] + (row * A_LDH + c8 * 8) * 2,
                       A + (size_t)(br * 128 + row) * lda + kc * 64 + c8 * 8);
        }
        if (B_KN) {
            // B: [K,N] rows kc*64..+63, cols bc*128..+127
#pragma unroll
            for (int p = 0; p < 4; ++p) {
                int idx = p * 256 + tid;
                int row = idx >> 4, c8 = idx & 15;
                CP_ASYNC16(BsU[b] + (row * B_LDH_KN + c8 * 8) * 2,
                           B + (size_t)(kc * 64 + row) * ldb + bc * 128 + c8 * 8);
            }
        } else {
            // B: [N,K] rows bc*128..+127, cols kc*64..+63
#pragma unroll
            for (int p = 0; p < 4; ++p) {
                int idx = p * 256 + tid;
                int row = idx >> 3, c8 = idx & 7;
                CP_ASYNC16(BsU[b] + (row * A_LDH + c8 * 8) * 2,
                           B + (size_t)(bc * 128 + row) * ldb + kc * 64 + c8 * 8);
            }
        }
        CP_COMMIT();
    };

    issue_load(0, 0);

    int cur = 0;
    for (int kc = 0; kc < kChunks; ++kc) {
        if (kc + 1 < kChunks) { issue_load(cur ^ 1, kc + 1); CP_WAIT(1); }
        else                  { CP_WAIT(0); }
        __syncthreads();

        const __half* Asb = AsH[cur];
        const __half* Bsb = BsH[cur];
#pragma unroll
        for (int ks = 0; ks < 4; ++ks) {
            const int k0 = ks * 16;
            wmma::fragment<wmma::matrix_a, 16, 16, 16, __half, wmma::row_major> af[2];
#pragma unroll
            for (int i = 0; i < 2; i++)
                wmma::load_matrix_sync(af[i], Asb + (wr * 32 + i * 16) * A_LDH + k0, A_LDH);
            if (B_KN) {
                wmma::fragment<wmma::matrix_b, 16, 16, 16, __half, wmma::row_major> bf[4];
#pragma unroll
                for (int j = 0; j < 4; j++)
                    wmma::load_matrix_sync(bf[j], Bsb + k0 * B_LDH_KN + wc * 64 + j * 16, B_LDH_KN);
#pragma unroll
                for (int i = 0; i < 2; i++)
#pragma unroll
                    for (int j = 0; j < 4; j++)
                        wmma::mma_sync(acc[i][j], af[i], bf[j], acc[i][j]);
            } else {
                wmma::fragment<wmma::matrix_b, 16, 16, 16, __half, wmma::col_major> bf[4];
#pragma unroll
                for (int j = 0; j < 4; j++)
                    wmma::load_matrix_sync(bf[j], Bsb + (wc * 64 + j * 16) * A_LDH + k0, A_LDH);
#pragma unroll
                for (int i = 0; i < 2; i++)
#pragma unroll
                    for (int j = 0; j < 4; j++)
                        wmma::mma_sync(acc[i][j], af[i], bf[j], acc[i][j]);
            }
        }
        __syncthreads();
        cur ^= 1;
    }

    if (!OUT_HALF) {
        // direct fp32 store
#pragma unroll
        for (int i = 0; i < 2; i++)
#pragma unroll
            for (int j = 0; j < 4; j++) {
#pragma unroll
                for (int t = 0; t < acc[i][j].num_elements; t++) acc[i][j].x[t] *= scale;
                float* cp = Cf + (size_t)(br * 128 + wr * 32 + i * 16) * ldc + bc * 128 + wc * 64 + j * 16;
                wmma::store_matrix_sync(cp, acc[i][j], ldc, wmma::mem_row_major);
            }
    } else {
        // stage fp32 in smem, convert to half, write global
        float* stg = (float*)smc;
#pragma unroll
        for (int i = 0; i < 2; i++)
#pragma unroll
            for (int j = 0; j < 4; j++)
                wmma::store_matrix_sync(stg + (size_t)(wr * 32 + i * 16) * STG_LD + wc * 64 + j * 16,
                                        acc[i][j], STG_LD, wmma::mem_row_major);
        __syncthreads();
        const int row = tid >> 1;
        const int cb = (tid & 1) * 64;
        const float* srow = stg + (size_t)row * STG_LD + cb;
        __half2* drow = (__half2*)(Ch + (size_t)(br * 128 + row) * ldc + bc * 128 + cb);
#pragma unroll
        for (int c = 0; c < 32; ++c)
            drow[c] = __floats2half2_rn(srow[2 * c], srow[2 * c + 1]);
    }
}

// ---------------------------------------------------------------------------
// Kernel 0: fp32 -> fp16 conversion (grid-stride over 4-elem groups)
// ---------------------------------------------------------------------------
__global__ void __launch_bounds__(256)
f2h_kernel(const float* __restrict__ s, __half* __restrict__ d, int n4)
{
    int i = blockIdx.x * 256 + threadIdx.x;
    if (i < n4) {
        float4 v = *(const float4*)(s + (size_t)i * 4);
        __half2* o = (__half2*)(d + (size_t)i * 4);
        o[0] = __floats2half2_rn(v.x, v.y);
        o[1] = __floats2half2_rn(v.z, v.w);
    }
}

// ---------------------------------------------------------------------------
// Kernel 1: QKV projections. grid = (8, 64, 3). Wh = [C,H] -> B_KN, out half
// ---------------------------------------------------------------------------
__global__ void __launch_bounds__(256, 2)
qkv_h()
{
    __half* Out;
    if (blockIdx.z == 0)      Out = g_Qh;
    else if (blockIdx.z == 1) Out = g_Kh;
    else                      Out = g_Vh;
    wmma_tile_h<true, true>(g_Xh, CN, g_Wh[blockIdx.z], HN,
                            nullptr, Out, HN, CN / 64, blockIdx.y, blockIdx.x, 1.0f);
}

// ---------------------------------------------------------------------------
// Kernel 2: S = Qh Kh^T * scale, causal block skip. grid = (16,16,BSZ). B_NK
// ---------------------------------------------------------------------------
__global__ void __launch_bounds__(256, 2)
scores_h()
{
    if (blockIdx.x > blockIdx.y) return;
    const int b = blockIdx.z;
    const __half* Q = g_Qh + (size_t)b * TN * HN;
    const __half* K = g_Kh + (size_t)b * TN * HN;
    float* S = g_S + (size_t)b * TN * TN;
    wmma_tile_h<false, false>(Q, HN, K, HN, S, nullptr, TN, HN / 64,
                              blockIdx.y, blockIdx.x, 0.03125f);
}

// ---------------------------------------------------------------------------
// Kernel 3: causal softmax; reads fp32 S, writes fp16 P (padded). grid (TN,BSZ)
// ---------------------------------------------------------------------------
__global__ void __launch_bounds__(256)
softmax_h()
{
    const int t = blockIdx.x;
    const int b = blockIdx.y;
    const float* row = g_S + ((size_t)b * TN + t) * TN;
    __half* prow = g_Ph + ((size_t)b * TN + t) * TN;
    const int n = t + 1;
    const int tid = threadIdx.x;

    __shared__ float red[8];

    float m = -INFINITY;
    for (int i = tid; i < n; i += 256) m = fmaxf(m, row[i]);
#pragma unroll
    for (int o = 16; o > 0; o >>= 1) m = fmaxf(m, __shfl_xor_sync(0xffffffffu, m, o));
    if ((tid & 31) == 0) red[tid >> 5] = m;
    __syncthreads();
    m = -INFINITY;
#pragma unroll
    for (int w = 0; w < 8; w++) m = fmaxf(m, red[w]);
    __syncthreads();

    float s = 0.f;
    for (int i = tid; i < n; i += 256) s += expf(row[i] - m);
#pragma unroll
    for (int o = 16; o > 0; o >>= 1) s += __shfl_xor_sync(0xffffffffu, s, o);
    if ((tid & 31) == 0) red[tid >> 5] = s;
    __syncthreads();
    s = 0.f;
#pragma unroll
    for (int w = 0; w < 8; w++) s += red[w];

    const float inv = 1.0f / s;
    for (int i = tid; i < n; i += 256) prow[i] = __float2half(expf(row[i] - m) * inv);

    const int npad = ((t >> 7) + 1) << 7;
    for (int i = n + tid; i < npad; i += 256) prow[i] = __float2half(0.f);
}

// ---------------------------------------------------------------------------
// Kernel 4: O = Ph Vh, k truncated at diagonal. grid (8,16,BSZ). B_KN, fp32 out
// ---------------------------------------------------------------------------
__global__ void __launch_bounds__(256, 2)
pv_h(float* __restrict__ out)
{
    const int b = blockIdx.z;
    const __half* P = g_Ph + (size_t)b * TN * TN;
    const __half* V = g_Vh + (size_t)b * TN * HN;
    float* O = out + (size_t)b * TN * HN;
    const int kChunks = (blockIdx.y + 1) * 2;   // (br+1)*128 / 64
    wmma_tile_h<true, false>(P, TN, V, HN, O, nullptr, HN, kChunks,
                             blockIdx.y, blockIdx.x, 1.0f);
}

// ---------------------------------------------------------------------------
extern "C" void kernel_launch(void* const* d_in, const int* in_sizes, int n_in,
                              void* d_out, int out_size)
{
    const float* x  = (const float*)d_in[0];
    const float* Wk = (const float*)d_in[1];
    const float* Wq = (const float*)d_in[2];
    const float* Wv = (const float*)d_in[3];
    float* out = (float*)d_out;

    cudaFuncSetAttribute(qkv_h,    cudaFuncAttributeMaxDynamicSharedMemorySize, SMEM_BYTES);
    cudaFuncSetAttribute(scores_h, cudaFuncAttributeMaxDynamicSharedMemorySize, SMEM_BYTES);
    cudaFuncSetAttribute(pv_h,     cudaFuncAttributeMaxDynamicSharedMemorySize, SMEM_BYTES);

    __half* xh; cudaGetSymbolAddress((void**)&xh, g_Xh);
    __half* wh; cudaGetSymbolAddress((void**)&wh, g_Wh);

    const int nX4 = BSZ * TN * CN / 4;
    const int nW4 = CN * HN / 4;
    f2h_kernel<<<(nX4 + 255) / 256, 256>>>(x,  xh, nX4);
    f2h_kernel<<<(nW4 + 255) / 256, 256>>>(Wq, wh + 0 * (size_t)CN * HN, nW4);
    f2h_kernel<<<(nW4 + 255) / 256, 256>>>(Wk, wh + 1 * (size_t)CN * HN, nW4);
    f2h_kernel<<<(nW4 + 255) / 256, 256>>>(Wv, wh + 2 * (size_t)CN * HN, nW4);

    qkv_h<<<dim3(HN / 128, (BSZ * TN) / 128, 3), 256, SMEM_BYTES>>>();
    scores_h<<<dim3(TN / 128, TN / 128, BSZ), 256, SMEM_BYTES>>>();
    softmax_h<<<dim3(TN, BSZ), 256>>>();
    pv_h<<<dim3(HN / 128, TN / 128, BSZ), 256, SMEM_BYTES>>>(out);
}